// round 1
// baseline (speedup 1.0000x reference)
#include <cuda_runtime.h>
#include <math.h>

#define BB 4
#define TT 48
#define NN 2000
#define BN (BB*NN)      // 8000
#define FF 16
#define HH 64
#define NHEADS 4
#define HD 16
#define HOR 24
#define PP 32
#define FT (FF*TT)      // 768

// ---------------- scratch (device globals: no allocation) ----------------
__device__ float g_hT[FT*BN];      // conv features, k-major [768][8000]
__device__ float g_projT[FT*HH];   // proj_w transposed [768][64]
__device__ float g_z[BN*HH];
__device__ float g_node[BN*HH];
__device__ float g_src[BN*PP];
__device__ float g_dst[BN*PP];
__device__ float g_qkv[BN*3*HH];
__device__ float g_yattn[BN*HH];
__device__ float g_y[BN*HH];
__device__ float g_y2[BN*HH];
__device__ unsigned g_maskbits[BB*NN*64];   // 64 words per row (2016 bits, 2000 used)

__device__ __forceinline__ float dot4(float4 a, float4 b) {
    return a.x*b.x + a.y*b.y + a.z*b.z + a.w*b.w;
}

// ---------------- 1) conv1d(SAME,K=3) + BN(eval) + ReLU -> g_hT ----------------
__global__ __launch_bounds__(256) void k_conv(const float* __restrict__ x,
                                              const float* __restrict__ cw,
                                              const float* __restrict__ cb,
                                              const float* __restrict__ bng,
                                              const float* __restrict__ bnb) {
    int node = blockIdx.x * 256 + threadIdx.x;
    int t = blockIdx.y;
    if (node >= BN) return;
    int b = node / NN, n = node - b * NN;
    const float* xb = x + b * (TT * NN) + n;
    float xm1 = (t > 0)      ? xb[(t - 1) * NN] : 0.f;
    float x0  =                xb[t * NN];
    float xp1 = (t < TT - 1) ? xb[(t + 1) * NN] : 0.f;
    float bns = rsqrtf(1.0f + 1e-5f);
#pragma unroll
    for (int f = 0; f < FF; f++) {
        float v = cw[f*3]*xm1 + cw[f*3+1]*x0 + cw[f*3+2]*xp1 + cb[f];
        v = v * (bng[f] * bns) + bnb[f];
        g_hT[(f * TT + t) * BN + node] = fmaxf(v, 0.f);
    }
}

// ---------------- 2) transpose proj_w [64][768] -> [768][64] ----------------
__global__ __launch_bounds__(256) void k_transw(const float* __restrict__ w) {
    int idx = blockIdx.x * 256 + threadIdx.x;
    if (idx < FT * HH) {
        int k = idx >> 6, h = idx & 63;
        g_projT[idx] = w[h * FT + k];
    }
}

// ---------------- 3) z = flat @ proj_w^T + b  (tiled SGEMM, M-tile 64) ----------------
__global__ __launch_bounds__(256) void k_proj(const float* __restrict__ pb) {
    __shared__ float Asm[32][64];
    __shared__ float Bsm[32][64];
    int t = threadIdx.x;
    int m0 = blockIdx.x * 64;
    int tx = t & 15, ty = t >> 4;
    float c[4][4] = {};
    for (int k0 = 0; k0 < FT; k0 += 32) {
#pragma unroll
        for (int r = 0; r < 2; r++) {
            int idx = t + 256 * r;
            int row = idx >> 4, col = (idx & 15) << 2;
            *(float4*)&Asm[row][col] = *(const float4*)&g_hT[(k0 + row) * BN + m0 + col];
            *(float4*)&Bsm[row][col] = *(const float4*)&g_projT[(k0 + row) * HH + col];
        }
        __syncthreads();
#pragma unroll
        for (int kk = 0; kk < 32; kk++) {
            float4 a  = *(float4*)&Asm[kk][ty * 4];
            float4 b4 = *(float4*)&Bsm[kk][tx * 4];
            float av[4] = {a.x, a.y, a.z, a.w};
            float bv[4] = {b4.x, b4.y, b4.z, b4.w};
#pragma unroll
            for (int i = 0; i < 4; i++)
#pragma unroll
                for (int j = 0; j < 4; j++) c[i][j] += av[i] * bv[j];
        }
        __syncthreads();
    }
#pragma unroll
    for (int i = 0; i < 4; i++) {
        float4 o;
        o.x = c[i][0] + pb[tx*4+0];
        o.y = c[i][1] + pb[tx*4+1];
        o.z = c[i][2] + pb[tx*4+2];
        o.w = c[i][3] + pb[tx*4+3];
        *(float4*)&g_z[(m0 + ty * 4 + i) * HH + tx * 4] = o;
    }
}

// ---------------- 4) LayerNorm + ReLU -> g_node ----------------
__global__ __launch_bounds__(256) void k_ln1(const float* __restrict__ g,
                                             const float* __restrict__ bb) {
    int w = threadIdx.x >> 5, lane = threadIdx.x & 31;
    int m = blockIdx.x * 8 + w;
    float v0 = g_z[m * 64 + lane], v1 = g_z[m * 64 + 32 + lane];
    float s = v0 + v1;
#pragma unroll
    for (int off = 16; off; off >>= 1) s += __shfl_xor_sync(0xffffffffu, s, off);
    float mean = s * (1.f / 64.f);
    float d0 = v0 - mean, d1 = v1 - mean;
    float vs = d0 * d0 + d1 * d1;
#pragma unroll
    for (int off = 16; off; off >>= 1) vs += __shfl_xor_sync(0xffffffffu, vs, off);
    float rs = rsqrtf(vs * (1.f / 64.f) + 1e-5f);
    g_node[m * 64 + lane]      = fmaxf(d0 * rs * g[lane]      + bb[lane],      0.f);
    g_node[m * 64 + 32 + lane] = fmaxf(d1 * rs * g[lane + 32] + bb[lane + 32], 0.f);
}

// ---------------- 5) src/dst (leaky 0.2) + qkv, fused ----------------
__global__ __launch_bounds__(256) void k_sdq(const float* __restrict__ sw, const float* __restrict__ sb,
                                             const float* __restrict__ dw, const float* __restrict__ db,
                                             const float* __restrict__ iw, const float* __restrict__ ib) {
    __shared__ float nsm[64 * 64];
    int t = threadIdx.x;
    int m0 = blockIdx.x * 64;
#pragma unroll
    for (int r = 0; r < 4; r++) {
        int idx = (t + 256 * r) * 4;
        *(float4*)&nsm[idx] = *(const float4*)&g_node[m0 * 64 + idx];
    }
    __syncthreads();
    const float* wrow; float bias;
    if (t < 32)       { wrow = sw + t * 64;        bias = sb[t]; }
    else if (t < 64)  { wrow = dw + (t - 32) * 64; bias = db[t - 32]; }
    else              { wrow = iw + (t - 64) * 64; bias = ib[t - 64]; }
    float4 wr[16];
#pragma unroll
    for (int r = 0; r < 16; r++) wr[r] = *(const float4*)&wrow[r * 4];
    for (int m = 0; m < 64; m++) {
        float acc = bias;
#pragma unroll
        for (int r = 0; r < 16; r++) {
            float4 nv = *(float4*)&nsm[m * 64 + r * 4];
            acc += dot4(wr[r], nv);
        }
        int gm = m0 + m;
        if (t < 64) {
            acc = (acc > 0.f) ? acc : 0.2f * acc;
            if (t < 32) g_src[gm * 32 + t] = acc;
            else        g_dst[gm * 32 + t - 32] = acc;
        } else {
            g_qkv[gm * 192 + t - 64] = acc;
        }
    }
}

// ---------------- 6) attention-1: flash-style, warp per (b,h,q) ----------------
__global__ __launch_bounds__(256) void k_attn1() {
    __shared__ float Ksm[128][20];
    __shared__ float Vsm[128][20];
    int t = threadIdx.x, w = t >> 5, lane = t & 31;
    int b = blockIdx.z, h = blockIdx.y;
    int q = blockIdx.x * 8 + w;
    const float* qkv_b = g_qkv + b * (NN * 192);
    float4 qr[4];
    {
        const float* qp = qkv_b + q * 192 + h * 16;
#pragma unroll
        for (int r = 0; r < 4; r++) qr[r] = *(const float4*)&qp[r * 4];
    }
    float mx = -1e30f, l = 0.f;
    float acc[16] = {};
    int jld = t >> 1, part = t & 1;
    for (int j0 = 0; j0 < NN; j0 += 128) {
        int row = j0 + jld;
        if (row < NN) {
            const float* kp = qkv_b + row * 192 + 64 + h * 16 + part * 8;
            const float* vp = kp + 64;
            *(float4*)&Ksm[jld][part * 8]     = *(const float4*)kp;
            *(float4*)&Ksm[jld][part * 8 + 4] = *(const float4*)&kp[4];
            *(float4*)&Vsm[jld][part * 8]     = *(const float4*)vp;
            *(float4*)&Vsm[jld][part * 8 + 4] = *(const float4*)&vp[4];
        }
        __syncthreads();
        float s[4];
#pragma unroll
        for (int c = 0; c < 4; c++) {
            int jj = lane + 32 * c;
            float4 k0 = *(float4*)&Ksm[jj][0];
            float4 k1 = *(float4*)&Ksm[jj][4];
            float4 k2 = *(float4*)&Ksm[jj][8];
            float4 k3 = *(float4*)&Ksm[jj][12];
            float d = dot4(qr[0], k0) + dot4(qr[1], k1) + dot4(qr[2], k2) + dot4(qr[3], k3);
            s[c] = 0.25f * d;
            if (j0 + jj >= NN) s[c] = -1e30f;
        }
        float tmax = fmaxf(fmaxf(s[0], s[1]), fmaxf(s[2], s[3]));
#pragma unroll
        for (int off = 16; off; off >>= 1) tmax = fmaxf(tmax, __shfl_xor_sync(0xffffffffu, tmax, off));
        float newm = fmaxf(mx, tmax);
        float f = __expf(mx - newm);
        l *= f;
#pragma unroll
        for (int d = 0; d < 16; d++) acc[d] *= f;
#pragma unroll
        for (int c = 0; c < 4; c++) {
            float p = __expf(s[c] - newm);
            l += p;
            int jj = lane + 32 * c;
            float4 v0 = *(float4*)&Vsm[jj][0];
            float4 v1 = *(float4*)&Vsm[jj][4];
            float4 v2 = *(float4*)&Vsm[jj][8];
            float4 v3 = *(float4*)&Vsm[jj][12];
            acc[0]+=p*v0.x; acc[1]+=p*v0.y; acc[2]+=p*v0.z; acc[3]+=p*v0.w;
            acc[4]+=p*v1.x; acc[5]+=p*v1.y; acc[6]+=p*v1.z; acc[7]+=p*v1.w;
            acc[8]+=p*v2.x; acc[9]+=p*v2.y; acc[10]+=p*v2.z; acc[11]+=p*v2.w;
            acc[12]+=p*v3.x; acc[13]+=p*v3.y; acc[14]+=p*v3.z; acc[15]+=p*v3.w;
        }
        mx = newm;
        __syncthreads();
    }
#pragma unroll
    for (int off = 16; off; off >>= 1) {
        l += __shfl_xor_sync(0xffffffffu, l, off);
#pragma unroll
        for (int d = 0; d < 16; d++) acc[d] += __shfl_xor_sync(0xffffffffu, acc[d], off);
    }
    if (lane == 0) {
        float inv = 1.f / l;
        float* op = g_yattn + (b * NN + q) * 64 + h * 16;
#pragma unroll
        for (int r = 0; r < 4; r++) {
            float4 o = make_float4(acc[4*r]*inv, acc[4*r+1]*inv, acc[4*r+2]*inv, acc[4*r+3]*inv);
            *(float4*)&op[r * 4] = o;
        }
    }
}

// ---------------- 7) out projection y = y_attn @ out_w^T + out_b ----------------
__global__ __launch_bounds__(256) void k_outp(const float* __restrict__ ow,
                                              const float* __restrict__ ob) {
    __shared__ float ysm[64 * 64];
    int t = threadIdx.x;
    int m0 = blockIdx.x * 64;
#pragma unroll
    for (int r = 0; r < 4; r++) {
        int idx = (t + 256 * r) * 4;
        *(float4*)&ysm[idx] = *(const float4*)&g_yattn[m0 * 64 + idx];
    }
    __syncthreads();
    int o = t & 63, gq = t >> 6;
    float4 wr[16];
#pragma unroll
    for (int r = 0; r < 16; r++) wr[r] = *(const float4*)&ow[o * 64 + r * 4];
    float bias = ob[o];
    for (int rr = 0; rr < 16; rr++) {
        int mm = gq * 16 + rr;
        float acc = bias;
#pragma unroll
        for (int r = 0; r < 16; r++) {
            float4 nv = *(float4*)&ysm[mm * 64 + r * 4];
            acc += dot4(wr[r], nv);
        }
        g_y[(m0 + mm) * 64 + o] = acc;
    }
}

// ---------------- 8) adjacency mask bits (norm pass + ballot pass) ----------------
__global__ __launch_bounds__(256) void k_mask(const float* __restrict__ es) {
    __shared__ float ssm[32][36];
    __shared__ float dsm[64][36];
    __shared__ float normsm[32];
    int t = threadIdx.x, w = t >> 5, lane = t & 31;
    int b = blockIdx.y;
    int q0 = blockIdx.x * 32;
    float scale = es[0];
    {
        int row = t >> 3, col = (t & 7) << 2;
        int q = q0 + row;
        float4 v = make_float4(0.f, 0.f, 0.f, 0.f);
        if (q < NN) v = *(const float4*)&g_src[(b * NN + q) * 32 + col];
        *(float4*)&ssm[row][col] = v;
    }
    __syncthreads();
    float sumsq[4] = {};
    for (int jt = 0; jt < 32; jt++) {
        int j0 = jt * 64;
#pragma unroll
        for (int r = 0; r < 2; r++) {
            int idx = t + 256 * r;
            int row = idx >> 3, col = (idx & 7) << 2;
            int jg = j0 + row;
            float4 v = make_float4(0.f, 0.f, 0.f, 0.f);
            if (jg < NN) v = *(const float4*)&g_dst[(b * NN + jg) * 32 + col];
            *(float4*)&dsm[row][col] = v;
        }
        __syncthreads();
#pragma unroll
        for (int c = 0; c < 4; c++) {
            int qq = w * 4 + c;
            float4 qv[8];
#pragma unroll
            for (int r = 0; r < 8; r++) qv[r] = *(float4*)&ssm[qq][r * 4];
#pragma unroll
            for (int half = 0; half < 2; half++) {
                int jj = lane + 32 * half;
                float s = 0.f;
#pragma unroll
                for (int r = 0; r < 8; r++) s += dot4(qv[r], *(float4*)&dsm[jj][r * 4]);
                if (j0 + jj < NN) sumsq[c] += s * s;
            }
        }
        __syncthreads();
    }
#pragma unroll
    for (int c = 0; c < 4; c++) {
        float red = sumsq[c];
#pragma unroll
        for (int off = 16; off; off >>= 1) red += __shfl_xor_sync(0xffffffffu, red, off);
        if (lane == 0) normsm[w * 4 + c] = fmaxf(sqrtf(red) * fabsf(scale), 1e-12f);
    }
    __syncthreads();
    for (int jt = 0; jt < 32; jt++) {
        int j0 = jt * 64;
#pragma unroll
        for (int r = 0; r < 2; r++) {
            int idx = t + 256 * r;
            int row = idx >> 3, col = (idx & 7) << 2;
            int jg = j0 + row;
            float4 v = make_float4(0.f, 0.f, 0.f, 0.f);
            if (jg < NN) v = *(const float4*)&g_dst[(b * NN + jg) * 32 + col];
            *(float4*)&dsm[row][col] = v;
        }
        __syncthreads();
#pragma unroll
        for (int c = 0; c < 4; c++) {
            int qq = w * 4 + c;
            int q = q0 + qq;
            float inv = scale / normsm[qq];
            float4 qv[8];
#pragma unroll
            for (int r = 0; r < 8; r++) qv[r] = *(float4*)&ssm[qq][r * 4];
#pragma unroll
            for (int half = 0; half < 2; half++) {
                int jj = lane + 32 * half;
                float s = 0.f;
#pragma unroll
                for (int r = 0; r < 8; r++) s += dot4(qv[r], *(float4*)&dsm[jj][r * 4]);
                float val = s * inv + ((j0 + jj) == q ? 1.f : 0.f);
                unsigned word = __ballot_sync(0xffffffffu, val <= 0.f);
                if (lane == 0 && q < NN) g_maskbits[(b * NN + q) * 64 + jt * 2 + half] = word;
            }
        }
        __syncthreads();
    }
}

// ---------------- 9) attention-2 (adjacency-masked), warp per (b,q) ----------------
__global__ __launch_bounds__(256) void k_attn2() {
    __shared__ float ysm[64 * 68];
    int t = threadIdx.x, w = t >> 5, lane = t & 31;
    int b = blockIdx.y;
    int q = blockIdx.x * 8 + w;
    const float* yb = g_y + b * (NN * 64);
    const unsigned* mrow = g_maskbits + (b * NN + q) * 64;
    float4 qr[16];
#pragma unroll
    for (int r = 0; r < 16; r++) qr[r] = *(const float4*)&yb[q * 64 + r * 4];
    float mx = -1e30f, l = 0.f;
    float accx = 0.f, accy = 0.f;
    for (int j0 = 0; j0 < NN; j0 += 64) {
#pragma unroll
        for (int r = 0; r < 4; r++) {
            int idx = t + 256 * r;
            int row = idx >> 4, col = (idx & 15) << 2;
            int jg = j0 + row;
            float4 v = (jg < NN) ? *(const float4*)&yb[jg * 64 + col]
                                 : make_float4(0.f, 0.f, 0.f, 0.f);
            *(float4*)&ysm[row * 68 + col] = v;
        }
        __syncthreads();
        unsigned w0 = mrow[(j0 >> 5)];
        unsigned w1 = mrow[(j0 >> 5) + 1];
        float s0 = 0.f, s1 = 0.f;
#pragma unroll
        for (int r = 0; r < 16; r++) {
            float4 k0 = *(float4*)&ysm[lane * 68 + r * 4];
            float4 k1 = *(float4*)&ysm[(lane + 32) * 68 + r * 4];
            s0 += dot4(qr[r], k0);
            s1 += dot4(qr[r], k1);
        }
        s0 = s0 * 0.125f + (((w0 >> lane) & 1u) ? -1e9f : 0.f);
        s1 = s1 * 0.125f + (((w1 >> lane) & 1u) ? -1e9f : 0.f);
        if (j0 + lane >= NN)      s0 = -1e30f;
        if (j0 + 32 + lane >= NN) s1 = -1e30f;
        float tmax = fmaxf(s0, s1);
#pragma unroll
        for (int off = 16; off; off >>= 1) tmax = fmaxf(tmax, __shfl_xor_sync(0xffffffffu, tmax, off));
        float newm = fmaxf(mx, tmax);
        float f = __expf(mx - newm);
        l *= f; accx *= f; accy *= f;
        float p0 = __expf(s0 - newm), p1 = __expf(s1 - newm);
        l += p0 + p1;
#pragma unroll
        for (int jj = 0; jj < 32; jj++) {
            float pj = __shfl_sync(0xffffffffu, p0, jj);
            float2 yv = *(float2*)&ysm[jj * 68 + 2 * lane];
            accx += pj * yv.x; accy += pj * yv.y;
        }
#pragma unroll
        for (int jj = 0; jj < 32; jj++) {
            float pj = __shfl_sync(0xffffffffu, p1, jj);
            float2 yv = *(float2*)&ysm[(jj + 32) * 68 + 2 * lane];
            accx += pj * yv.x; accy += pj * yv.y;
        }
        mx = newm;
        __syncthreads();
    }
    float lt = l;
#pragma unroll
    for (int off = 16; off; off >>= 1) lt += __shfl_xor_sync(0xffffffffu, lt, off);
    float inv = 1.f / lt;
    float2 o = make_float2(accx * inv, accy * inv);
    *(float2*)&g_y2[(b * NN + q) * 64 + 2 * lane] = o;
}

// ---------------- 10) residual + LN(lnA) + horizon predictor ----------------
__global__ __launch_bounds__(256) void k_final(const float* __restrict__ lg,
                                               const float* __restrict__ lb,
                                               const float* __restrict__ pw,
                                               const float* __restrict__ pb,
                                               float* __restrict__ out) {
    __shared__ float rsm[8][64];
    __shared__ float pwsm[64 * 24];
    int t = threadIdx.x, w = t >> 5, lane = t & 31;
    int m = blockIdx.x * 8 + w;
    for (int idx = t; idx < 24 * 64; idx += 256) {
        int o = idx >> 6, d = idx & 63;
        pwsm[d * 24 + o] = pw[idx];
    }
    float v0 = g_y2[m * 64 + lane]      + g_node[m * 64 + lane];
    float v1 = g_y2[m * 64 + 32 + lane] + g_node[m * 64 + 32 + lane];
    float s = v0 + v1;
#pragma unroll
    for (int off = 16; off; off >>= 1) s += __shfl_xor_sync(0xffffffffu, s, off);
    float mean = s * (1.f / 64.f);
    float d0 = v0 - mean, d1 = v1 - mean;
    float vs = d0 * d0 + d1 * d1;
#pragma unroll
    for (int off = 16; off; off >>= 1) vs += __shfl_xor_sync(0xffffffffu, vs, off);
    float rs = rsqrtf(vs * (1.f / 64.f) + 1e-5f);
    rsm[w][lane]      = d0 * rs * lg[lane]      + lb[lane];
    rsm[w][lane + 32] = d1 * rs * lg[lane + 32] + lb[lane + 32];
    __syncthreads();
    if (lane < 24) {
        float acc = pb[lane];
#pragma unroll
        for (int d = 0; d < 64; d++) acc += rsm[w][d] * pwsm[d * 24 + lane];
        out[m * 24 + lane] = acc;
    }
}

// ---------------- launch ----------------
extern "C" void kernel_launch(void* const* d_in, const int* in_sizes, int n_in,
                              void* d_out, int out_size) {
    const float* x        = (const float*)d_in[0];
    const float* conv_w   = (const float*)d_in[1];
    const float* conv_b   = (const float*)d_in[2];
    const float* bn_g     = (const float*)d_in[3];
    const float* bn_b     = (const float*)d_in[4];
    const float* proj_w   = (const float*)d_in[5];
    const float* proj_b   = (const float*)d_in[6];
    const float* ln1_g    = (const float*)d_in[7];
    const float* ln1_b    = (const float*)d_in[8];
    const float* src_w    = (const float*)d_in[9];
    const float* src_b    = (const float*)d_in[10];
    const float* dst_w    = (const float*)d_in[11];
    const float* dst_b    = (const float*)d_in[12];
    const float* edge_sc  = (const float*)d_in[13];
    const float* inp_w    = (const float*)d_in[14];
    const float* inp_b    = (const float*)d_in[15];
    const float* out_w    = (const float*)d_in[16];
    const float* out_b    = (const float*)d_in[17];
    const float* lnA_g    = (const float*)d_in[18];
    const float* lnA_b    = (const float*)d_in[19];
    const float* pred_w   = (const float*)d_in[20];
    const float* pred_b   = (const float*)d_in[21];
    float* out = (float*)d_out;

    k_conv<<<dim3((BN + 255) / 256, TT), 256>>>(x, conv_w, conv_b, bn_g, bn_b);
    k_transw<<<(FT * HH + 255) / 256, 256>>>(proj_w);
    k_proj<<<BN / 64, 256>>>(proj_b);
    k_ln1<<<BN / 8, 256>>>(ln1_g, ln1_b);
    k_sdq<<<BN / 64, 256>>>(src_w, src_b, dst_w, dst_b, inp_w, inp_b);
    k_attn1<<<dim3(NN / 8, NHEADS, BB), 256>>>();
    k_outp<<<BN / 64, 256>>>(out_w, out_b);
    k_mask<<<dim3((NN + 31) / 32, BB), 256>>>(edge_sc);
    k_attn2<<<dim3(NN / 8, BB), 256>>>();
    k_final<<<BN / 8, 256>>>(lnA_g, lnA_b, pred_w, pred_b, out);
}

// round 2
// speedup vs baseline: 1.2097x; 1.2097x over previous
#include <cuda_runtime.h>
#include <math.h>

#define BB 4
#define TT 48
#define NN 2000
#define BN (BB*NN)      // 8000
#define FF 16
#define HH 64
#define NHEADS 4
#define HD 16
#define HOR 24
#define PP 32
#define FT (FF*TT)      // 768

// ---------------- scratch (device globals: no allocation) ----------------
__device__ float g_hT[FT*BN];      // conv features, k-major [768][8000]
__device__ float g_projT[FT*HH];   // proj_w transposed [768][64]
__device__ float g_z[BN*HH];
__device__ float g_node[BN*HH];
__device__ float g_src[BN*PP];
__device__ float g_dst[BN*PP];
__device__ float g_qkv[BN*3*HH];
__device__ float g_yattn[BN*HH];
__device__ float g_y[BN*HH];
__device__ float g_y2[BN*HH];
__device__ unsigned g_maskbits[BB*NN*64];   // 64 words per row

__device__ __forceinline__ float dot4(float4 a, float4 b) {
    return a.x*b.x + a.y*b.y + a.z*b.z + a.w*b.w;
}
__device__ __forceinline__ void cp_async16(void* smem, const void* gmem) {
    unsigned s = (unsigned)__cvta_generic_to_shared(smem);
    asm volatile("cp.async.cg.shared.global [%0], [%1], 16;\n" :: "r"(s), "l"(gmem));
}
__device__ __forceinline__ void cp_commit() { asm volatile("cp.async.commit_group;\n"); }
template<int N> __device__ __forceinline__ void cp_wait() {
    asm volatile("cp.async.wait_group %0;\n" :: "n"(N));
}
__device__ __forceinline__ float4 shfl_xor_f4(float4 v, int m) {
    float4 r;
    r.x = __shfl_xor_sync(0xffffffffu, v.x, m);
    r.y = __shfl_xor_sync(0xffffffffu, v.y, m);
    r.z = __shfl_xor_sync(0xffffffffu, v.z, m);
    r.w = __shfl_xor_sync(0xffffffffu, v.w, m);
    return r;
}

// ---------------- 1) conv1d(SAME,K=3) + BN(eval) + ReLU -> g_hT ----------------
__global__ __launch_bounds__(256) void k_conv(const float* __restrict__ x,
                                              const float* __restrict__ cw,
                                              const float* __restrict__ cb,
                                              const float* __restrict__ bng,
                                              const float* __restrict__ bnb) {
    int node = blockIdx.x * 256 + threadIdx.x;
    int t = blockIdx.y;
    if (node >= BN) return;
    int b = node / NN, n = node - b * NN;
    const float* xb = x + b * (TT * NN) + n;
    float xm1 = (t > 0)      ? xb[(t - 1) * NN] : 0.f;
    float x0  =                xb[t * NN];
    float xp1 = (t < TT - 1) ? xb[(t + 1) * NN] : 0.f;
    float bns = rsqrtf(1.0f + 1e-5f);
#pragma unroll
    for (int f = 0; f < FF; f++) {
        float v = cw[f*3]*xm1 + cw[f*3+1]*x0 + cw[f*3+2]*xp1 + cb[f];
        v = v * (bng[f] * bns) + bnb[f];
        g_hT[(f * TT + t) * BN + node] = fmaxf(v, 0.f);
    }
}

// ---------------- 2) transpose proj_w [64][768] -> [768][64] ----------------
__global__ __launch_bounds__(256) void k_transw(const float* __restrict__ w) {
    int idx = blockIdx.x * 256 + threadIdx.x;
    if (idx < FT * HH) {
        int k = idx >> 6, h = idx & 63;
        g_projT[idx] = w[h * FT + k];
    }
}

// ---------------- 3) z = flat @ proj_w^T + b (tiled SGEMM, double-buffered) ----------------
__global__ __launch_bounds__(256) void k_proj(const float* __restrict__ pb) {
    __shared__ float Asm[2][32][64];
    __shared__ float Bsm[2][32][64];
    int t = threadIdx.x;
    int m0 = blockIdx.x * 64;
    int tx = t & 15, ty = t >> 4;
    int lrow0 = t >> 4, lcol0 = (t & 15) << 2;
    int lrow1 = (t + 256) >> 4, lcol1 = ((t + 256) & 15) << 2;
    float c[4][4] = {};

    const int NT = FT / 32;  // 24
    // prefetch tile 0
    cp_async16(&Asm[0][lrow0][lcol0], &g_hT[lrow0 * BN + m0 + lcol0]);
    cp_async16(&Asm[0][lrow1][lcol1], &g_hT[lrow1 * BN + m0 + lcol1]);
    cp_async16(&Bsm[0][lrow0][lcol0], &g_projT[lrow0 * HH + lcol0]);
    cp_async16(&Bsm[0][lrow1][lcol1], &g_projT[lrow1 * HH + lcol1]);
    cp_commit();

    for (int it = 0; it < NT; it++) {
        if (it + 1 < NT) {
            int k0 = (it + 1) * 32, nb = (it + 1) & 1;
            cp_async16(&Asm[nb][lrow0][lcol0], &g_hT[(k0 + lrow0) * BN + m0 + lcol0]);
            cp_async16(&Asm[nb][lrow1][lcol1], &g_hT[(k0 + lrow1) * BN + m0 + lcol1]);
            cp_async16(&Bsm[nb][lrow0][lcol0], &g_projT[(k0 + lrow0) * HH + lcol0]);
            cp_async16(&Bsm[nb][lrow1][lcol1], &g_projT[(k0 + lrow1) * HH + lcol1]);
            cp_commit();
            cp_wait<1>();
        } else {
            cp_wait<0>();
        }
        __syncthreads();
        int buf = it & 1;
#pragma unroll
        for (int kk = 0; kk < 32; kk++) {
            float4 a  = *(float4*)&Asm[buf][kk][ty * 4];
            float4 b4 = *(float4*)&Bsm[buf][kk][tx * 4];
            float av[4] = {a.x, a.y, a.z, a.w};
            float bv[4] = {b4.x, b4.y, b4.z, b4.w};
#pragma unroll
            for (int i = 0; i < 4; i++)
#pragma unroll
                for (int j = 0; j < 4; j++) c[i][j] += av[i] * bv[j];
        }
        __syncthreads();
    }
#pragma unroll
    for (int i = 0; i < 4; i++) {
        float4 o;
        o.x = c[i][0] + pb[tx*4+0];
        o.y = c[i][1] + pb[tx*4+1];
        o.z = c[i][2] + pb[tx*4+2];
        o.w = c[i][3] + pb[tx*4+3];
        *(float4*)&g_z[(m0 + ty * 4 + i) * HH + tx * 4] = o;
    }
}

// ---------------- 4) LayerNorm + ReLU -> g_node ----------------
__global__ __launch_bounds__(256) void k_ln1(const float* __restrict__ g,
                                             const float* __restrict__ bb) {
    int w = threadIdx.x >> 5, lane = threadIdx.x & 31;
    int m = blockIdx.x * 8 + w;
    float v0 = g_z[m * 64 + lane], v1 = g_z[m * 64 + 32 + lane];
    float s = v0 + v1;
#pragma unroll
    for (int off = 16; off; off >>= 1) s += __shfl_xor_sync(0xffffffffu, s, off);
    float mean = s * (1.f / 64.f);
    float d0 = v0 - mean, d1 = v1 - mean;
    float vs = d0 * d0 + d1 * d1;
#pragma unroll
    for (int off = 16; off; off >>= 1) vs += __shfl_xor_sync(0xffffffffu, vs, off);
    float rs = rsqrtf(vs * (1.f / 64.f) + 1e-5f);
    g_node[m * 64 + lane]      = fmaxf(d0 * rs * g[lane]      + bb[lane],      0.f);
    g_node[m * 64 + 32 + lane] = fmaxf(d1 * rs * g[lane + 32] + bb[lane + 32], 0.f);
}

// ---------------- 5) src/dst (leaky 0.2) + qkv, fused ----------------
__global__ __launch_bounds__(256) void k_sdq(const float* __restrict__ sw, const float* __restrict__ sb,
                                             const float* __restrict__ dw, const float* __restrict__ db,
                                             const float* __restrict__ iw, const float* __restrict__ ib) {
    __shared__ float nsm[64 * 64];
    int t = threadIdx.x;
    int m0 = blockIdx.x * 64;
#pragma unroll
    for (int r = 0; r < 4; r++) {
        int idx = (t + 256 * r) * 4;
        *(float4*)&nsm[idx] = *(const float4*)&g_node[m0 * 64 + idx];
    }
    __syncthreads();
    const float* wrow; float bias;
    if (t < 32)       { wrow = sw + t * 64;        bias = sb[t]; }
    else if (t < 64)  { wrow = dw + (t - 32) * 64; bias = db[t - 32]; }
    else              { wrow = iw + (t - 64) * 64; bias = ib[t - 64]; }
    float4 wr[16];
#pragma unroll
    for (int r = 0; r < 16; r++) wr[r] = *(const float4*)&wrow[r * 4];
    for (int m = 0; m < 64; m++) {
        float acc = bias;
#pragma unroll
        for (int r = 0; r < 16; r++) {
            float4 nv = *(float4*)&nsm[m * 64 + r * 4];
            acc += dot4(wr[r], nv);
        }
        int gm = m0 + m;
        if (t < 64) {
            acc = (acc > 0.f) ? acc : 0.2f * acc;
            if (t < 32) g_src[gm * 32 + t] = acc;
            else        g_dst[gm * 32 + t - 32] = acc;
        } else {
            g_qkv[gm * 192 + t - 64] = acc;
        }
    }
}

// ---------------- 6) attention-1: flash-style, warp per (b,h,q), cp.async double-buffer ----------------
__global__ __launch_bounds__(256) void k_attn1() {
    __shared__ float Ksm[2][128][20];
    __shared__ float Vsm[2][128][20];
    int t = threadIdx.x, w = t >> 5, lane = t & 31;
    int b = blockIdx.z, h = blockIdx.y;
    int q = blockIdx.x * 8 + w;
    const float* qkv_b = g_qkv + b * (NN * 192);
    float4 qr[4];
    {
        const float* qp = qkv_b + q * 192 + h * 16;
#pragma unroll
        for (int r = 0; r < 4; r++) qr[r] = *(const float4*)&qp[r * 4];
    }
    int jld = t >> 1, part = t & 1;
    const int NT = (NN + 127) / 128;  // 16

    auto prefetch = [&](int buf, int j0) {
        int row = j0 + jld;
        if (row > NN - 1) row = NN - 1;
        const float* kp = qkv_b + row * 192 + 64 + h * 16 + part * 8;
        cp_async16(&Ksm[buf][jld][part * 8],     kp);
        cp_async16(&Ksm[buf][jld][part * 8 + 4], kp + 4);
        cp_async16(&Vsm[buf][jld][part * 8],     kp + 64);
        cp_async16(&Vsm[buf][jld][part * 8 + 4], kp + 68);
    };

    prefetch(0, 0); cp_commit();

    float mx = -1e30f, l = 0.f;
    float acc[16] = {};
    for (int it = 0; it < NT; it++) {
        int j0 = it * 128;
        if (it + 1 < NT) { prefetch((it + 1) & 1, j0 + 128); cp_commit(); cp_wait<1>(); }
        else             { cp_wait<0>(); }
        __syncthreads();
        int buf = it & 1;
        float s[4];
#pragma unroll
        for (int c = 0; c < 4; c++) {
            int jj = lane + 32 * c;
            float4 k0 = *(float4*)&Ksm[buf][jj][0];
            float4 k1 = *(float4*)&Ksm[buf][jj][4];
            float4 k2 = *(float4*)&Ksm[buf][jj][8];
            float4 k3 = *(float4*)&Ksm[buf][jj][12];
            float d = dot4(qr[0], k0) + dot4(qr[1], k1) + dot4(qr[2], k2) + dot4(qr[3], k3);
            s[c] = 0.25f * d;
            if (j0 + jj >= NN) s[c] = -1e30f;
        }
        float tmax = fmaxf(fmaxf(s[0], s[1]), fmaxf(s[2], s[3]));
#pragma unroll
        for (int off = 16; off; off >>= 1) tmax = fmaxf(tmax, __shfl_xor_sync(0xffffffffu, tmax, off));
        if (tmax > mx) {
            float f = __expf(mx - tmax);
            l *= f;
#pragma unroll
            for (int d = 0; d < 16; d++) acc[d] *= f;
            mx = tmax;
        }
#pragma unroll
        for (int c = 0; c < 4; c++) {
            float p = __expf(s[c] - mx);
            l += p;
            int jj = lane + 32 * c;
            float4 v0 = *(float4*)&Vsm[buf][jj][0];
            float4 v1 = *(float4*)&Vsm[buf][jj][4];
            float4 v2 = *(float4*)&Vsm[buf][jj][8];
            float4 v3 = *(float4*)&Vsm[buf][jj][12];
            acc[0]+=p*v0.x; acc[1]+=p*v0.y; acc[2]+=p*v0.z; acc[3]+=p*v0.w;
            acc[4]+=p*v1.x; acc[5]+=p*v1.y; acc[6]+=p*v1.z; acc[7]+=p*v1.w;
            acc[8]+=p*v2.x; acc[9]+=p*v2.y; acc[10]+=p*v2.z; acc[11]+=p*v2.w;
            acc[12]+=p*v3.x; acc[13]+=p*v3.y; acc[14]+=p*v3.z; acc[15]+=p*v3.w;
        }
        __syncthreads();
    }
#pragma unroll
    for (int off = 16; off; off >>= 1) {
        l += __shfl_xor_sync(0xffffffffu, l, off);
#pragma unroll
        for (int d = 0; d < 16; d++) acc[d] += __shfl_xor_sync(0xffffffffu, acc[d], off);
    }
    if (lane == 0) {
        float inv = 1.f / l;
        float* op = g_yattn + (b * NN + q) * 64 + h * 16;
#pragma unroll
        for (int r = 0; r < 4; r++) {
            float4 o = make_float4(acc[4*r]*inv, acc[4*r+1]*inv, acc[4*r+2]*inv, acc[4*r+3]*inv);
            *(float4*)&op[r * 4] = o;
        }
    }
}

// ---------------- 7) out projection y = y_attn @ out_w^T + out_b ----------------
__global__ __launch_bounds__(256) void k_outp(const float* __restrict__ ow,
                                              const float* __restrict__ ob) {
    __shared__ float ysm[64 * 64];
    int t = threadIdx.x;
    int m0 = blockIdx.x * 64;
#pragma unroll
    for (int r = 0; r < 4; r++) {
        int idx = (t + 256 * r) * 4;
        *(float4*)&ysm[idx] = *(const float4*)&g_yattn[m0 * 64 + idx];
    }
    __syncthreads();
    int o = t & 63, gq = t >> 6;
    float4 wr[16];
#pragma unroll
    for (int r = 0; r < 16; r++) wr[r] = *(const float4*)&ow[o * 64 + r * 4];
    float bias = ob[o];
    for (int rr = 0; rr < 16; rr++) {
        int mm = gq * 16 + rr;
        float acc = bias;
#pragma unroll
        for (int r = 0; r < 16; r++) {
            float4 nv = *(float4*)&ysm[mm * 64 + r * 4];
            acc += dot4(wr[r], nv);
        }
        g_y[(m0 + mm) * 64 + o] = acc;
    }
}

// ---------------- 8) adjacency mask bits (norm pass + ballot pass, cp.async) ----------------
__global__ __launch_bounds__(256) void k_mask(const float* __restrict__ es) {
    __shared__ float ssm[32][36];
    __shared__ float dsm[2][64][36];
    __shared__ float normsm[32];
    int t = threadIdx.x, w = t >> 5, lane = t & 31;
    int b = blockIdx.y;
    int q0 = blockIdx.x * 32;
    float scale = es[0];
    {
        int row = t >> 3, col = (t & 7) << 2;
        int q = q0 + row;
        float4 v = make_float4(0.f, 0.f, 0.f, 0.f);
        if (q < NN) v = *(const float4*)&g_src[(b * NN + q) * 32 + col];
        *(float4*)&ssm[row][col] = v;
    }
    int lrow0 = t >> 3, lcol0 = (t & 7) << 2;
    int lrow1 = (t + 256) >> 3, lcol1 = ((t + 256) & 7) << 2;
    auto prefetch = [&](int buf, int j0) {
        int r0 = j0 + lrow0; if (r0 > NN - 1) r0 = NN - 1;
        int r1 = j0 + lrow1; if (r1 > NN - 1) r1 = NN - 1;
        cp_async16(&dsm[buf][lrow0][lcol0], &g_dst[(b * NN + r0) * 32 + lcol0]);
        cp_async16(&dsm[buf][lrow1][lcol1], &g_dst[(b * NN + r1) * 32 + lcol1]);
    };

    const int NJT = 32;
    // ---------------- pass 1: row norms ----------------
    prefetch(0, 0); cp_commit();
    float sumsq[4] = {};
    for (int jt = 0; jt < NJT; jt++) {
        int j0 = jt * 64;
        if (jt + 1 < NJT) { prefetch((jt + 1) & 1, j0 + 64); cp_commit(); cp_wait<1>(); }
        else              { cp_wait<0>(); }
        __syncthreads();
        int buf = jt & 1;
#pragma unroll
        for (int c = 0; c < 4; c++) {
            int qq = w * 4 + c;
            float4 qv[8];
#pragma unroll
            for (int r = 0; r < 8; r++) qv[r] = *(float4*)&ssm[qq][r * 4];
#pragma unroll
            for (int half = 0; half < 2; half++) {
                int jj = lane + 32 * half;
                float s = 0.f;
#pragma unroll
                for (int r = 0; r < 8; r++) s += dot4(qv[r], *(float4*)&dsm[buf][jj][r * 4]);
                if (j0 + jj < NN) sumsq[c] += s * s;
            }
        }
        __syncthreads();
    }
#pragma unroll
    for (int c = 0; c < 4; c++) {
        float red = sumsq[c];
#pragma unroll
        for (int off = 16; off; off >>= 1) red += __shfl_xor_sync(0xffffffffu, red, off);
        if (lane == 0) normsm[w * 4 + c] = fmaxf(sqrtf(red) * fabsf(scale), 1e-12f);
    }
    __syncthreads();
    // ---------------- pass 2: ballot mask bits ----------------
    prefetch(0, 0); cp_commit();
    for (int jt = 0; jt < NJT; jt++) {
        int j0 = jt * 64;
        if (jt + 1 < NJT) { prefetch((jt + 1) & 1, j0 + 64); cp_commit(); cp_wait<1>(); }
        else              { cp_wait<0>(); }
        __syncthreads();
        int buf = jt & 1;
#pragma unroll
        for (int c = 0; c < 4; c++) {
            int qq = w * 4 + c;
            int q = q0 + qq;
            float inv = scale / normsm[qq];
            float4 qv[8];
#pragma unroll
            for (int r = 0; r < 8; r++) qv[r] = *(float4*)&ssm[qq][r * 4];
#pragma unroll
            for (int half = 0; half < 2; half++) {
                int jj = lane + 32 * half;
                float s = 0.f;
#pragma unroll
                for (int r = 0; r < 8; r++) s += dot4(qv[r], *(float4*)&dsm[buf][jj][r * 4]);
                float val = s * inv + ((j0 + jj) == q ? 1.f : 0.f);
                unsigned word = __ballot_sync(0xffffffffu, val <= 0.f);
                if (lane == 0 && q < NN) g_maskbits[(b * NN + q) * 64 + jt * 2 + half] = word;
            }
        }
        __syncthreads();
    }
}

// ---------------- 9) attention-2 (adjacency-masked), lane-owns-keys, cp.async ----------------
__global__ __launch_bounds__(256) void k_attn2() {
    __shared__ float ysm[2][64][68];
    __shared__ float qsm[8][68];
    int t = threadIdx.x, w = t >> 5, lane = t & 31;
    int b = blockIdx.y;
    int q = blockIdx.x * 8 + w;
    const float* yb = g_y + b * (NN * 64);
    const unsigned* mrow = g_maskbits + (b * NN + q) * 64;
    // load this warp's query row into qsm[w]
    *(float2*)&qsm[w][2 * lane] = *(const float2*)&yb[q * 64 + 2 * lane];

    int lrow0 = t >> 4, lcol0 = (t & 15) << 2;
    auto prefetch = [&](int buf, int j0) {
#pragma unroll
        for (int r = 0; r < 4; r++) {
            int row = lrow0 + 16 * r;
            int grow = j0 + row; if (grow > NN - 1) grow = NN - 1;
            cp_async16(&ysm[buf][row][lcol0], &yb[grow * 64 + lcol0]);
        }
    };

    const int NT = (NN + 63) / 64;  // 32
    prefetch(0, 0); cp_commit();

    float mx = -1e30f, lsum = 0.f;
    float4 acc4[16];
#pragma unroll
    for (int r = 0; r < 16; r++) acc4[r] = make_float4(0.f, 0.f, 0.f, 0.f);

    for (int it = 0; it < NT; it++) {
        int j0 = it * 64;
        if (it + 1 < NT) { prefetch((it + 1) & 1, j0 + 64); cp_commit(); cp_wait<1>(); }
        else             { cp_wait<0>(); }
        __syncthreads();
        int buf = it & 1;
        unsigned w0 = mrow[it * 2];
        unsigned w1 = mrow[it * 2 + 1];
        float s0 = 0.f, s1 = 0.f;
#pragma unroll
        for (int r = 0; r < 16; r++) {
            float4 qv = *(float4*)&qsm[w][r * 4];
            float4 k0 = *(float4*)&ysm[buf][lane][r * 4];
            float4 k1 = *(float4*)&ysm[buf][lane + 32][r * 4];
            s0 += dot4(qv, k0);
            s1 += dot4(qv, k1);
        }
        s0 = s0 * 0.125f + (((w0 >> lane) & 1u) ? -1e9f : 0.f);
        s1 = s1 * 0.125f + (((w1 >> lane) & 1u) ? -1e9f : 0.f);
        if (j0 + lane >= NN)      s0 = -1e30f;
        if (j0 + 32 + lane >= NN) s1 = -1e30f;
        float tmax = fmaxf(s0, s1);
#pragma unroll
        for (int off = 16; off; off >>= 1) tmax = fmaxf(tmax, __shfl_xor_sync(0xffffffffu, tmax, off));
        if (tmax > mx) {
            float f = __expf(mx - tmax);
            lsum *= f;
#pragma unroll
            for (int r = 0; r < 16; r++) {
                acc4[r].x *= f; acc4[r].y *= f; acc4[r].z *= f; acc4[r].w *= f;
            }
            mx = tmax;
        }
        float p0 = __expf(s0 - mx), p1 = __expf(s1 - mx);
        lsum += p0 + p1;
#pragma unroll
        for (int r = 0; r < 16; r++) {
            float4 v0 = *(float4*)&ysm[buf][lane][r * 4];
            float4 v1 = *(float4*)&ysm[buf][lane + 32][r * 4];
            acc4[r].x += p0 * v0.x + p1 * v1.x;
            acc4[r].y += p0 * v0.y + p1 * v1.y;
            acc4[r].z += p0 * v0.z + p1 * v1.z;
            acc4[r].w += p0 * v0.w + p1 * v1.w;
        }
        __syncthreads();
    }
    // total normalizer
#pragma unroll
    for (int off = 16; off; off >>= 1) lsum += __shfl_xor_sync(0xffffffffu, lsum, off);
    float inv = 1.f / lsum;
    // halving butterfly: lane ends owning dims 2*lane, 2*lane+1
#pragma unroll
    for (int r = 0; r < 8; r++) {
        float4 send = (lane & 16) ? acc4[r] : acc4[r + 8];
        float4 oth = shfl_xor_f4(send, 16);
        float4 keep = (lane & 16) ? acc4[r + 8] : acc4[r];
        acc4[r] = make_float4(keep.x + oth.x, keep.y + oth.y, keep.z + oth.z, keep.w + oth.w);
    }
#pragma unroll
    for (int r = 0; r < 4; r++) {
        float4 send = (lane & 8) ? acc4[r] : acc4[r + 4];
        float4 oth = shfl_xor_f4(send, 8);
        float4 keep = (lane & 8) ? acc4[r + 4] : acc4[r];
        acc4[r] = make_float4(keep.x + oth.x, keep.y + oth.y, keep.z + oth.z, keep.w + oth.w);
    }
#pragma unroll
    for (int r = 0; r < 2; r++) {
        float4 send = (lane & 4) ? acc4[r] : acc4[r + 2];
        float4 oth = shfl_xor_f4(send, 4);
        float4 keep = (lane & 4) ? acc4[r + 2] : acc4[r];
        acc4[r] = make_float4(keep.x + oth.x, keep.y + oth.y, keep.z + oth.z, keep.w + oth.w);
    }
    {
        float4 send = (lane & 2) ? acc4[0] : acc4[1];
        float4 oth = shfl_xor_f4(send, 2);
        float4 keep = (lane & 2) ? acc4[1] : acc4[0];
        acc4[0] = make_float4(keep.x + oth.x, keep.y + oth.y, keep.z + oth.z, keep.w + oth.w);
    }
    {
        float2 send = (lane & 1) ? make_float2(acc4[0].x, acc4[0].y) : make_float2(acc4[0].z, acc4[0].w);
        float2 oth;
        oth.x = __shfl_xor_sync(0xffffffffu, send.x, 1);
        oth.y = __shfl_xor_sync(0xffffffffu, send.y, 1);
        float2 keep = (lane & 1) ? make_float2(acc4[0].z, acc4[0].w) : make_float2(acc4[0].x, acc4[0].y);
        float2 res = make_float2((keep.x + oth.x) * inv, (keep.y + oth.y) * inv);
        *(float2*)&g_y2[(b * NN + q) * 64 + 2 * lane] = res;
    }
}

// ---------------- 10) residual + LN(lnA) + horizon predictor ----------------
__global__ __launch_bounds__(256) void k_final(const float* __restrict__ lg,
                                               const float* __restrict__ lb,
                                               const float* __restrict__ pw,
                                               const float* __restrict__ pb,
                                               float* __restrict__ out) {
    __shared__ float rsm[8][64];
    __shared__ float pwsm[64 * 24];
    int t = threadIdx.x, w = t >> 5, lane = t & 31;
    int m = blockIdx.x * 8 + w;
    for (int idx = t; idx < 24 * 64; idx += 256) {
        int o = idx >> 6, d = idx & 63;
        pwsm[d * 24 + o] = pw[idx];
    }
    float v0 = g_y2[m * 64 + lane]      + g_node[m * 64 + lane];
    float v1 = g_y2[m * 64 + 32 + lane] + g_node[m * 64 + 32 + lane];
    float s = v0 + v1;
#pragma unroll
    for (int off = 16; off; off >>= 1) s += __shfl_xor_sync(0xffffffffu, s, off);
    float mean = s * (1.f / 64.f);
    float d0 = v0 - mean, d1 = v1 - mean;
    float vs = d0 * d0 + d1 * d1;
#pragma unroll
    for (int off = 16; off; off >>= 1) vs += __shfl_xor_sync(0xffffffffu, vs, off);
    float rs = rsqrtf(vs * (1.f / 64.f) + 1e-5f);
    rsm[w][lane]      = d0 * rs * lg[lane]      + lb[lane];
    rsm[w][lane + 32] = d1 * rs * lg[lane + 32] + lb[lane + 32];
    __syncthreads();
    if (lane < 24) {
        float acc = pb[lane];
#pragma unroll
        for (int d = 0; d < 64; d++) acc += rsm[w][d] * pwsm[d * 24 + lane];
        out[m * 24 + lane] = acc;
    }
}

// ---------------- launch ----------------
extern "C" void kernel_launch(void* const* d_in, const int* in_sizes, int n_in,
                              void* d_out, int out_size) {
    const float* x        = (const float*)d_in[0];
    const float* conv_w   = (const float*)d_in[1];
    const float* conv_b   = (const float*)d_in[2];
    const float* bn_g     = (const float*)d_in[3];
    const float* bn_b     = (const float*)d_in[4];
    const float* proj_w   = (const float*)d_in[5];
    const float* proj_b   = (const float*)d_in[6];
    const float* ln1_g    = (const float*)d_in[7];
    const float* ln1_b    = (const float*)d_in[8];
    const float* src_w    = (const float*)d_in[9];
    const float* src_b    = (const float*)d_in[10];
    const float* dst_w    = (const float*)d_in[11];
    const float* dst_b    = (const float*)d_in[12];
    const float* edge_sc  = (const float*)d_in[13];
    const float* inp_w    = (const float*)d_in[14];
    const float* inp_b    = (const float*)d_in[15];
    const float* out_w    = (const float*)d_in[16];
    const float* out_b    = (const float*)d_in[17];
    const float* lnA_g    = (const float*)d_in[18];
    const float* lnA_b    = (const float*)d_in[19];
    const float* pred_w   = (const float*)d_in[20];
    const float* pred_b   = (const float*)d_in[21];
    float* out = (float*)d_out;

    k_conv<<<dim3((BN + 255) / 256, TT), 256>>>(x, conv_w, conv_b, bn_g, bn_b);
    k_transw<<<(FT * HH + 255) / 256, 256>>>(proj_w);
    k_proj<<<BN / 64, 256>>>(proj_b);
    k_ln1<<<BN / 8, 256>>>(ln1_g, ln1_b);
    k_sdq<<<BN / 64, 256>>>(src_w, src_b, dst_w, dst_b, inp_w, inp_b);
    k_attn1<<<dim3(NN / 8, NHEADS, BB), 256>>>();
    k_outp<<<BN / 64, 256>>>(out_w, out_b);
    k_mask<<<dim3((NN + 31) / 32, BB), 256>>>(edge_sc);
    k_attn2<<<dim3(NN / 8, BB), 256>>>();
    k_final<<<BN / 8, 256>>>(lnA_g, lnA_b, pred_w, pred_b, out);
}